// round 4
// baseline (speedup 1.0000x reference)
#include <cuda_runtime.h>
#include <math.h>

#define BATCH 8
#define FEAT 512
#define NUM 512
#define KK 32
#define NSPLIT 4
#define NBLK 256

typedef unsigned long long ull;

// ---------------- device scratch (static, allocation-free) ----------------
__device__ float g_a[BATCH * NUM * KK];               // softmax assignments a[b][n][k]
__device__ float g_axp[NSPLIT * BATCH * FEAT * KK];   // partial ax  [s][b][f][k]
__device__ float g_ax2p[NSPLIT * BATCH * FEAT * KK];  // partial ax2 [s][b][f][k]
__device__ float g_asump[BATCH * 32 * KK];            // asum partials per 16-n tile
__device__ float g_ssqp[BATCH * 64 * 2];              // global-norm partials [b][fg][fv1/fv2]
__device__ unsigned g_cnt = 0;                        // barrier arrival counter (self-resets)
__device__ unsigned g_gen = 0;                        // barrier generation (monotonic, replay-safe)

__device__ __forceinline__ float wsum(float v) {
#pragma unroll
    for (int o = 16; o; o >>= 1) v += __shfl_xor_sync(0xffffffffu, v, o);
    return v;
}
__device__ __forceinline__ float wmax(float v) {
#pragma unroll
    for (int o = 16; o; o >>= 1) v = fmaxf(v, __shfl_xor_sync(0xffffffffu, v, o));
    return v;
}

// packed f32x2 helpers (sm_100+)
__device__ __forceinline__ ull pk(float lo, float hi) {
    ull r;
    asm("mov.b64 %0, {%1, %2};" : "=l"(r) : "f"(lo), "f"(hi));
    return r;
}
__device__ __forceinline__ void upk(float& lo, float& hi, ull v) {
    asm("mov.b64 {%0, %1}, %2;" : "=f"(lo), "=f"(hi) : "l"(v));
}
__device__ __forceinline__ void ffma2(ull& d, ull a, ull b) {
    asm("fma.rn.f32x2 %0, %1, %2, %0;" : "+l"(d) : "l"(a), "l"(b));
}

// Replay-safe grid barrier: counter self-resets, generation only grows.
// Safe across consecutive barriers (waiters poll gen, never cnt).
__device__ __forceinline__ void gridbar() {
    __syncthreads();
    if (threadIdx.x == 0) {
        __threadfence();
        unsigned gen = atomicAdd(&g_gen, 0u);
        if (atomicAdd(&g_cnt, 1u) == NBLK - 1u) {
            *((volatile unsigned*)&g_cnt) = 0u;
            __threadfence();
            atomicAdd(&g_gen, 1u);
        } else {
            while (atomicAdd(&g_gen, 0u) == gen) __nanosleep(32);
        }
        __threadfence();
    }
    __syncthreads();
}

// shared-memory phase union
struct P1 {
    float W_s[KK][65];     // pad 65: conflict-free per-lane stride
    float X_s[64][16];     // [f_local][n_local], 16 n's per CTA
    float red[8][KK];
};
struct P2 {
    float A_s[32][32];
    float X_s[64][33];     // stride 33: conflict-free per-lane f
    float X2_s[64][33];
};
struct P3 {
    float s1s[2][8], s2s[2][8];
    float scs[2];
};
union SMU {
    P1 p1;
    P2 p2;
    P3 p3;
};

// ---------------- single persistent kernel: 3 phases, 2 grid barriers --------
__global__ __launch_bounds__(256, 2) void k_all(const float* __restrict__ x,
                                                const float* __restrict__ W,
                                                const float* __restrict__ bias,
                                                const float* __restrict__ mu,
                                                const float* __restrict__ sigma,
                                                float* __restrict__ out) {
    __shared__ __align__(16) SMU sm;
    const int tid  = threadIdx.x;
    const int w    = tid >> 5;
    const int lane = tid & 31;
    const int bx   = blockIdx.x;

    // ================= PHASE 1: logits + softmax + asum partials =============
    // all 256 CTAs: (b = bx>>5, 16-n tile = bx&31). Warp owns 2 n's (one f32x2).
    {
        const int b    = bx >> 5;
        const int tile = bx & 31;
        const int n0   = tile * 16;

        ull acc = 0ULL;

        for (int t = 0; t < 8; t++) {
            const int fb = t * 64;
            for (int idx = tid; idx < 32 * 64; idx += 256) {
                int k = idx >> 6, fl = idx & 63;
                sm.p1.W_s[k][fl] = W[k * FEAT + fb + fl];
            }
            for (int idx = tid; idx < 64 * 16; idx += 256) {
                int fl = idx >> 4, nl = idx & 15;
                sm.p1.X_s[fl][nl] = x[((size_t)b * FEAT + fb + fl) * NUM + n0 + nl];
            }
            __syncthreads();
#pragma unroll 8
            for (int fl = 0; fl < 64; fl++) {
                float wv = sm.p1.W_s[lane][fl];                                          // conflict-free
                ull   wvv = pk(wv, wv);
                ull   xp = *reinterpret_cast<const ull*>(&sm.p1.X_s[fl][w * 2]);          // broadcast
                ffma2(acc, wvv, xp);
            }
            __syncthreads();
        }

        float l0, l1;
        upk(l0, l1, acc);
        const float bv = bias[lane];
        float pa = 0.f;
        {
            float lg = l0 + bv;
            float m = wmax(lg);
            float e = __expf(lg - m);
            float s = wsum(e);
            float a = e / s;
            g_a[((size_t)b * NUM + n0 + w * 2) * KK + lane] = a;
            pa += a;
        }
        {
            float lg = l1 + bv;
            float m = wmax(lg);
            float e = __expf(lg - m);
            float s = wsum(e);
            float a = e / s;
            g_a[((size_t)b * NUM + n0 + w * 2 + 1) * KK + lane] = a;
            pa += a;
        }
        sm.p1.red[w][lane] = pa;
        __syncthreads();
        if (tid < 32) {
            float s = 0.f;
#pragma unroll
            for (int g = 0; g < 8; g++) s += sm.p1.red[g][tid];
            g_asump[((size_t)b * 32 + tile) * KK + tid] = s;
        }
    }

    gridbar();

    // ================= PHASE 2: ax / ax2 GEMM partials ========================
    {
        const int ft = bx & 7;
        const int s  = (bx >> 3) & 3;
        const int b  = bx >> 5;
        const int f0 = ft * 64;
        const int nb = s * 128;
        const int fw = w & 1, kg = w >> 1;
        const int fl = fw * 32 + lane;     // f within tile
        const int kbase = kg * 8;          // 8 k's = 4 packed pairs per thread

        ull acc1[4] = {0ULL, 0ULL, 0ULL, 0ULL};
        ull acc2[4] = {0ULL, 0ULL, 0ULL, 0ULL};

        for (int c = 0; c < 4; c++) {
            const int n0 = nb + c * 32;
            for (int idx = tid; idx < 1024; idx += 256) {
                int nl = idx >> 5, k = idx & 31;
                sm.p2.A_s[nl][k] = g_a[((size_t)b * NUM + n0 + nl) * KK + k];
            }
            for (int idx = tid; idx < 2048; idx += 256) {
                int fr = idx >> 5, nc = idx & 31;
                float v = x[((size_t)b * FEAT + f0 + fr) * NUM + n0 + nc];
                sm.p2.X_s[fr][nc]  = v;
                sm.p2.X2_s[fr][nc] = v * v;
            }
            __syncthreads();
#pragma unroll 4
            for (int nl = 0; nl < 32; nl++) {
                float xv  = sm.p2.X_s[fl][nl];    // stride 33 -> conflict-free
                float x2v = sm.p2.X2_s[fl][nl];
                ull xvv  = pk(xv, xv);
                ull x2vv = pk(x2v, x2v);
                ulonglong2 a01 = *reinterpret_cast<const ulonglong2*>(&sm.p2.A_s[nl][kbase]);     // broadcast
                ulonglong2 a23 = *reinterpret_cast<const ulonglong2*>(&sm.p2.A_s[nl][kbase + 4]); // broadcast
                ffma2(acc1[0], a01.x, xvv);  ffma2(acc2[0], a01.x, x2vv);
                ffma2(acc1[1], a01.y, xvv);  ffma2(acc2[1], a01.y, x2vv);
                ffma2(acc1[2], a23.x, xvv);  ffma2(acc2[2], a23.x, x2vv);
                ffma2(acc1[3], a23.y, xvv);  ffma2(acc2[3], a23.y, x2vv);
            }
            __syncthreads();
        }

        const size_t base = (((size_t)s * BATCH + b) * FEAT + f0 + fl) * KK + kbase;
        *reinterpret_cast<ulonglong2*>(&g_axp[base])      = make_ulonglong2(acc1[0], acc1[1]);
        *reinterpret_cast<ulonglong2*>(&g_axp[base + 4])  = make_ulonglong2(acc1[2], acc1[3]);
        *reinterpret_cast<ulonglong2*>(&g_ax2p[base])     = make_ulonglong2(acc2[0], acc2[1]);
        *reinterpret_cast<ulonglong2*>(&g_ax2p[base + 4]) = make_ulonglong2(acc2[2], acc2[3]);
    }

    gridbar();

    // ================= PHASE 3: fisher vectors + norms + output ==============
    // 256 CTAs, each handles 2 fg units (8 f's each): b = bx>>5, fgbase = (bx&31)*2.
    {
        const int b      = bx >> 5;
        const int fgbase = (bx & 31) * 2;

        // asum[b][k] from 32 per-tile partials (L2-hot)
        float asv = 0.f;
#pragma unroll
        for (int t = 0; t < 32; t++) asv += g_asump[((size_t)b * 32 + t) * KK + lane];

        float v1v[2], v2v[2];
#pragma unroll
        for (int j = 0; j < 2; j++) {
            const int f = (fgbase + j) * 8 + w;
            float ax = 0.f, ax2 = 0.f;
#pragma unroll
            for (int s = 0; s < NSPLIT; s++) {
                size_t po = (((size_t)s * BATCH + b) * FEAT + f) * KK + lane;
                ax  += g_axp[po];
                ax2 += g_ax2p[po];
            }
            float muv = mu[f * KK + lane];
            float sg  = sigma[f * KK + lane];
            float fv1 = (ax - muv * asv) / sg;
            float fv2 = (ax2 - 2.f * muv * ax + muv * muv * asv) / (sg * sg) - asv;

            float n1 = sqrtf(wsum(fv1 * fv1));
            float n2 = sqrtf(wsum(fv2 * fv2));
            float v1 = fv1 / fmaxf(n1, 1e-12f);
            float v2 = fv2 / fmaxf(n2, 1e-12f);
            v1v[j] = v1;
            v2v[j] = v2;

            float ssq1 = wsum(v1 * v1);
            float ssq2 = wsum(v2 * v2);
            if (lane == 0) { sm.p3.s1s[j][w] = ssq1; sm.p3.s2s[j][w] = ssq2; }
        }
        __syncthreads();
        if (tid < 2) {
            float t1 = 0.f, t2 = 0.f;
#pragma unroll
            for (int g = 0; g < 8; g++) { t1 += sm.p3.s1s[tid][g]; t2 += sm.p3.s2s[tid][g]; }
            g_ssqp[((size_t)b * 64 + fgbase + tid) * 2 + 0] = t1;
            g_ssqp[((size_t)b * 64 + fgbase + tid) * 2 + 1] = t2;
        }

        gridbar();

        // global scale per (b, half); warps 0/1 reduce 64 partials in fixed order
        if (w < 2) {
            float s = g_ssqp[((size_t)b * 64 + lane) * 2 + w]
                    + g_ssqp[((size_t)b * 64 + 32 + lane) * 2 + w];
            s = wsum(s);
            if (lane == 0) sm.p3.scs[w] = 1.f / fmaxf(sqrtf(s), 1e-12f);
        }
        __syncthreads();

        const size_t ob = (size_t)b * 2 * FEAT * KK;
        const float sc1 = sm.p3.scs[0];
        const float sc2 = sm.p3.scs[1];
#pragma unroll
        for (int j = 0; j < 2; j++) {
            const int f = (fgbase + j) * 8 + w;
            out[ob + (size_t)f * KK + lane]             = v1v[j] * sc1;
            out[ob + FEAT * KK + (size_t)f * KK + lane] = v2v[j] * sc2;
        }
    }
}

// ---------------- launch -----------------------------------------------------
extern "C" void kernel_launch(void* const* d_in, const int* in_sizes, int n_in,
                              void* d_out, int out_size) {
    (void)in_sizes; (void)n_in; (void)out_size;
    const float* x     = (const float*)d_in[0];
    const float* W     = (const float*)d_in[1];
    const float* bias  = (const float*)d_in[2];
    const float* mu    = (const float*)d_in[3];
    const float* sigma = (const float*)d_in[4];
    float* out = (float*)d_out;

    k_all<<<NBLK, 256>>>(x, W, bias, mu, sigma, out);
}

// round 5
// speedup vs baseline: 1.0811x; 1.0811x over previous
#include <cuda_runtime.h>
#include <math.h>

#define BATCH 8
#define FEAT 512
#define NUM 512
#define KK 32
#define NSPLIT 4
#define NBLK 256

typedef unsigned long long ull;

// 1/sqrt(512): global L2 scale is exact because every row is unit-norm after rownorm
#define GSC 0.04419417382415922f

// ---------------- device scratch (static, allocation-free) ----------------
__device__ float g_a[BATCH * NUM * KK];               // softmax assignments a[b][n][k]
__device__ float g_axp[NSPLIT * BATCH * FEAT * KK];   // partial ax  [s][b][f][k]
__device__ float g_ax2p[NSPLIT * BATCH * FEAT * KK];  // partial ax2 [s][b][f][k]
__device__ float g_asump[BATCH * 16 * KK];            // asum partials per 32-n tile
__device__ unsigned g_cnt = 0;                        // barrier counter (self-resets)
__device__ unsigned g_gen = 0;                        // barrier generation (monotonic, replay-safe)

__device__ __forceinline__ float wsum(float v) {
#pragma unroll
    for (int o = 16; o; o >>= 1) v += __shfl_xor_sync(0xffffffffu, v, o);
    return v;
}
__device__ __forceinline__ float wmax(float v) {
#pragma unroll
    for (int o = 16; o; o >>= 1) v = fmaxf(v, __shfl_xor_sync(0xffffffffu, v, o));
    return v;
}

// packed f32x2 helpers (sm_100+)
__device__ __forceinline__ ull pk(float lo, float hi) {
    ull r;
    asm("mov.b64 %0, {%1, %2};" : "=l"(r) : "f"(lo), "f"(hi));
    return r;
}
__device__ __forceinline__ void upk(float& lo, float& hi, ull v) {
    asm("mov.b64 {%0, %1}, %2;" : "=f"(lo), "=f"(hi) : "l"(v));
}
__device__ __forceinline__ void ffma2(ull& d, ull a, ull b) {
    asm("fma.rn.f32x2 %0, %1, %2, %0;" : "+l"(d) : "l"(a), "l"(b));
}
__device__ __forceinline__ ull fmul2(ull a, ull b) {
    ull r;
    asm("mul.rn.f32x2 %0, %1, %2;" : "=l"(r) : "l"(a), "l"(b));
    return r;
}

// Replay-safe grid barrier: counter self-resets, generation only grows.
__device__ __forceinline__ void gridbar() {
    __syncthreads();
    if (threadIdx.x == 0) {
        __threadfence();
        unsigned gen = atomicAdd(&g_gen, 0u);
        if (atomicAdd(&g_cnt, 1u) == NBLK - 1u) {
            *((volatile unsigned*)&g_cnt) = 0u;
            __threadfence();
            atomicAdd(&g_gen, 1u);
        } else {
            while (atomicAdd(&g_gen, 0u) == gen) __nanosleep(32);
        }
        __threadfence();
    }
    __syncthreads();
}

// shared-memory phase union
struct P1 {
    ull   W2[KK][65];      // W duplicated (w,w); 8B-stride 65 (odd) -> conflict-free
    float X_s[64][32];     // [f_local][n_local]
    float red[8][KK];
};
struct P2 {
    float A_s[32][32];     // [n_local][k]; k-pair b64/b128 loads are warp-broadcast
    ull   X2[64][33];      // x duplicated (x,x); 8B-stride 33 (odd) -> conflict-free
};
union SMU {
    P1 p1;
    P2 p2;
};

// ---------------- K_MAIN: softmax (128 CTAs) -> gridbar -> gemm (256 CTAs) ---
__global__ __launch_bounds__(256, 2) void k_main(const float* __restrict__ x,
                                                 const float* __restrict__ W,
                                                 const float* __restrict__ bias) {
    __shared__ __align__(16) SMU sm;
    const int tid  = threadIdx.x;
    const int w    = tid >> 5;
    const int lane = tid & 31;
    const int bx   = blockIdx.x;

    // ================= PHASE 1: logits + softmax + asum partials =============
    // 128 CTAs: (b = bx>>4, 32-n tile). Warp owns 4 n's (2 independent f32x2 accs).
    if (bx < 128) {
        const int b  = bx >> 4;
        const int n0 = (bx & 15) * 32;

        ull acc01 = 0ULL, acc23 = 0ULL;

        for (int t = 0; t < 8; t++) {
            const int fb = t * 64;
            for (int idx = tid; idx < 32 * 64; idx += 256) {
                int k = idx >> 6, fl = idx & 63;
                float wv = W[k * FEAT + fb + fl];
                sm.p1.W2[k][fl] = pk(wv, wv);
            }
            for (int idx = tid; idx < 64 * 32; idx += 256) {
                int fl = idx >> 5, nl = idx & 31;
                sm.p1.X_s[fl][nl] = x[((size_t)b * FEAT + fb + fl) * NUM + n0 + nl];
            }
            __syncthreads();
#pragma unroll 8
            for (int fl = 0; fl < 64; fl++) {
                ull wvv = sm.p1.W2[lane][fl];                                             // LDS64, conflict-free
                ulonglong2 xp = *reinterpret_cast<const ulonglong2*>(&sm.p1.X_s[fl][w * 4]); // LDS128 broadcast
                ffma2(acc01, wvv, xp.x);
                ffma2(acc23, wvv, xp.y);
            }
            __syncthreads();
        }

        float l[4];
        upk(l[0], l[1], acc01);
        upk(l[2], l[3], acc23);

        const float bv = bias[lane];
        float pa = 0.f;
#pragma unroll
        for (int j = 0; j < 4; j++) {
            float lg = l[j] + bv;
            float m = wmax(lg);
            float e = __expf(lg - m);
            float s = wsum(e);
            float a = e / s;
            int   n = n0 + w * 4 + j;
            g_a[((size_t)b * NUM + n) * KK + lane] = a;   // coalesced (k contiguous)
            pa += a;
        }
        sm.p1.red[w][lane] = pa;
        __syncthreads();
        if (tid < 32) {
            float s = 0.f;
#pragma unroll
            for (int g = 0; g < 8; g++) s += sm.p1.red[g][tid];
            g_asump[((size_t)b * 16 + (bx & 15)) * KK + tid] = s;
        }
    }

    gridbar();

    // ================= PHASE 2: ax / ax2 GEMM partials ========================
    {
        const int ft = bx & 7;
        const int s  = (bx >> 3) & 3;
        const int b  = bx >> 5;
        const int f0 = ft * 64;
        const int nb = s * 128;
        const int fw = w & 1, kg = w >> 1;
        const int fl = fw * 32 + lane;     // f within tile
        const int kbase = kg * 8;          // 8 k's = 4 packed pairs per thread

        ull acc1[4] = {0ULL, 0ULL, 0ULL, 0ULL};
        ull acc2[4] = {0ULL, 0ULL, 0ULL, 0ULL};

        for (int c = 0; c < 4; c++) {
            const int n0 = nb + c * 32;
            __syncthreads();
            for (int idx = tid; idx < 1024; idx += 256) {
                int nl = idx >> 5, k = idx & 31;
                sm.p2.A_s[nl][k] = g_a[((size_t)b * NUM + n0 + nl) * KK + k];
            }
            for (int idx = tid; idx < 2048; idx += 256) {
                int fr = idx >> 5, nc = idx & 31;
                float v = x[((size_t)b * FEAT + f0 + fr) * NUM + n0 + nc];
                sm.p2.X2[fr][nc] = pk(v, v);
            }
            __syncthreads();
#pragma unroll 4
            for (int nl = 0; nl < 32; nl++) {
                ull xvv  = sm.p2.X2[fl][nl];     // LDS64, conflict-free (odd 8B stride)
                ull x2vv = fmul2(xvv, xvv);      // packed x^2, no second smem array
                ulonglong2 a01 = *reinterpret_cast<const ulonglong2*>(&sm.p2.A_s[nl][kbase]);     // broadcast
                ulonglong2 a23 = *reinterpret_cast<const ulonglong2*>(&sm.p2.A_s[nl][kbase + 4]); // broadcast
                ffma2(acc1[0], a01.x, xvv);  ffma2(acc2[0], a01.x, x2vv);
                ffma2(acc1[1], a01.y, xvv);  ffma2(acc2[1], a01.y, x2vv);
                ffma2(acc1[2], a23.x, xvv);  ffma2(acc2[2], a23.x, x2vv);
                ffma2(acc1[3], a23.y, xvv);  ffma2(acc2[3], a23.y, x2vv);
            }
        }

        const size_t base = (((size_t)s * BATCH + b) * FEAT + f0 + fl) * KK + kbase;
        *reinterpret_cast<ulonglong2*>(&g_axp[base])      = make_ulonglong2(acc1[0], acc1[1]);
        *reinterpret_cast<ulonglong2*>(&g_axp[base + 4])  = make_ulonglong2(acc1[2], acc1[3]);
        *reinterpret_cast<ulonglong2*>(&g_ax2p[base])     = make_ulonglong2(acc2[0], acc2[1]);
        *reinterpret_cast<ulonglong2*>(&g_ax2p[base + 4]) = make_ulonglong2(acc2[2], acc2[3]);
    }
}

// ---------------- K_FV: fisher vectors + row norm + CONSTANT global scale ----
// grid 512 (b*64+fg), block 256, one f per warp. No barrier, single store pass.
__global__ __launch_bounds__(256, 4) void k_fv(const float* __restrict__ mu,
                                               const float* __restrict__ sigma,
                                               float* __restrict__ out) {
    const int bx = blockIdx.x;
    const int b  = bx >> 6;
    const int fg = bx & 63;
    const int tid = threadIdx.x, w = tid >> 5, lane = tid & 31;
    const int f = fg * 8 + w;

    // asum[b][k] from 16 per-tile partials (L2-hot)
    float asv = 0.f;
#pragma unroll
    for (int t = 0; t < 16; t++) asv += g_asump[((size_t)b * 16 + t) * KK + lane];

    float ax = 0.f, ax2 = 0.f;
#pragma unroll
    for (int s = 0; s < NSPLIT; s++) {
        size_t po = (((size_t)s * BATCH + b) * FEAT + f) * KK + lane;
        ax  += g_axp[po];
        ax2 += g_ax2p[po];
    }
    float muv = mu[f * KK + lane];
    float sg  = sigma[f * KK + lane];
    float fv1 = (ax - muv * asv) / sg;
    float fv2 = (ax2 - 2.f * muv * ax + muv * muv * asv) / (sg * sg) - asv;

    float n1 = sqrtf(wsum(fv1 * fv1));
    float n2 = sqrtf(wsum(fv2 * fv2));
    // rownorm then constant global scale (sum of 512 unit rows == 512 exactly)
    float v1 = fv1 / fmaxf(n1, 1e-12f) * GSC;
    float v2 = fv2 / fmaxf(n2, 1e-12f) * GSC;

    const size_t ob = (size_t)b * 2 * FEAT * KK;
    out[ob + (size_t)f * KK + lane]             = v1;
    out[ob + FEAT * KK + (size_t)f * KK + lane] = v2;
}

// ---------------- launch -----------------------------------------------------
extern "C" void kernel_launch(void* const* d_in, const int* in_sizes, int n_in,
                              void* d_out, int out_size) {
    (void)in_sizes; (void)n_in; (void)out_size;
    const float* x     = (const float*)d_in[0];
    const float* W     = (const float*)d_in[1];
    const float* bias  = (const float*)d_in[2];
    const float* mu    = (const float*)d_in[3];
    const float* sigma = (const float*)d_in[4];
    float* out = (float*)d_out;

    k_main<<<NBLK, 256>>>(x, W, bias);
    k_fv<<<512, 256>>>(mu, sigma, out);
}

// round 6
// speedup vs baseline: 1.3039x; 1.2061x over previous
#include <cuda_runtime.h>
#include <math.h>

#define BATCH 8
#define FEAT 512
#define NUM 512
#define KK 32
#define NSPLIT 4
#define NBLK 256

typedef unsigned long long ull;

// 1/sqrt(512): global L2 scale is exact (512 unit-norm rows per half)
#define GSC 0.04419417382415922f

// ---------------- device scratch (static, allocation-free) ----------------
__device__ float g_a[BATCH * NUM * KK];               // a[b][n][k]
__device__ float g_axp[NSPLIT * BATCH * FEAT * KK];   // partial ax  [s][b][f][k]
__device__ float g_ax2p[NSPLIT * BATCH * FEAT * KK];  // partial ax2 [s][b][f][k]
__device__ float g_asumt[BATCH * KK * 16];            // asum partials TRANSPOSED [b][k][tile]
__device__ unsigned g_cnt = 0;                        // barrier counter (self-resets)
__device__ unsigned g_gen = 0;                        // barrier generation (monotonic)

__device__ __forceinline__ float wsum(float v) {
#pragma unroll
    for (int o = 16; o; o >>= 1) v += __shfl_xor_sync(0xffffffffu, v, o);
    return v;
}
__device__ __forceinline__ float wmax(float v) {
#pragma unroll
    for (int o = 16; o; o >>= 1) v = fmaxf(v, __shfl_xor_sync(0xffffffffu, v, o));
    return v;
}

// packed f32x2 helpers (sm_100+)
__device__ __forceinline__ ull pk(float lo, float hi) {
    ull r;
    asm("mov.b64 %0, {%1, %2};" : "=l"(r) : "f"(lo), "f"(hi));
    return r;
}
__device__ __forceinline__ void upk(float& lo, float& hi, ull v) {
    asm("mov.b64 {%0, %1}, %2;" : "=f"(lo), "=f"(hi) : "l"(v));
}
__device__ __forceinline__ void ffma2(ull& d, ull a, ull b) {
    asm("fma.rn.f32x2 %0, %1, %2, %0;" : "+l"(d) : "l"(a), "l"(b));
}
__device__ __forceinline__ ull fmul2(ull a, ull b) {
    ull r;
    asm("mul.rn.f32x2 %0, %1, %2;" : "=l"(r) : "l"(a), "l"(b));
    return r;
}

// Replay-safe grid barrier. Waiters poll with volatile LOADS (no atomic-ALU
// contention on the release path); counter self-resets; generation monotonic.
__device__ __forceinline__ void gridbar() {
    __threadfence();            // every thread releases its own global stores
    __syncthreads();
    if (threadIdx.x == 0) {
        unsigned gen = *((volatile unsigned*)&g_gen);
        if (atomicAdd(&g_cnt, 1u) == NBLK - 1u) {
            *((volatile unsigned*)&g_cnt) = 0u;
            __threadfence();
            atomicAdd(&g_gen, 1u);
        } else {
            while (*((volatile unsigned*)&g_gen) == gen) __nanosleep(64);
        }
        __threadfence();
    }
    __syncthreads();
}

// shared-memory phase union
struct P1 {
    ull   W2[KK][65];      // W dup'd (w,w); odd 8B stride -> conflict-free LDS64
    float X_s[64][32];     // [f_local][n_local]; LDS128 warp-broadcast
    float red[8][KK];
};
struct P2 {
    float A_s[32][32];     // [n_local][k]; k-pair LDS128 warp-broadcast
    ull   X2[64][33];      // x dup'd; odd 8B stride -> conflict-free LDS64
};
union SMU {
    P1 p1;
    P2 p2;
};

// ---------------- single kernel: softmax -> bar -> gemm -> bar -> fv ---------
__global__ __launch_bounds__(256, 2) void k_all(const float* __restrict__ x,
                                                const float* __restrict__ W,
                                                const float* __restrict__ bias,
                                                const float* __restrict__ mu,
                                                const float* __restrict__ sigma,
                                                float* __restrict__ out) {
    __shared__ __align__(16) SMU sm;
    const int tid  = threadIdx.x;
    const int w    = tid >> 5;
    const int lane = tid & 31;
    const int bx   = blockIdx.x;

    // phase-2 coords (used for pre-barrier X prefetch too)
    const int ft2 = bx & 7;
    const int s2  = (bx >> 3) & 3;
    const int b2  = bx >> 5;
    const int f02 = ft2 * 64;
    const int nb2 = s2 * 128;

    // ================= PHASE 1: logits + softmax + asum partials =============
    // 128 CTAs: b = bx>>4, 32-n tile = bx&15. Warp owns 4 n's (2 f32x2 chains).
    if (bx < 128) {
        const int b    = bx >> 4;
        const int tile = bx & 15;
        const int n0   = tile * 32;

        ull acc01 = 0ULL, acc23 = 0ULL;

        // register prefetch buffers: 8 W + 8 X elements per thread per tile
        float wr[8], xr[8];
#pragma unroll
        for (int i = 0; i < 8; i++) {
            int idx = tid + i * 256;
            wr[i] = W[(idx >> 6) * FEAT + (idx & 63)];                            // fb = 0
            xr[i] = x[((size_t)b * FEAT + (idx >> 5)) * NUM + n0 + (idx & 31)];   // fb = 0
        }

        for (int t = 0; t < 8; t++) {
            __syncthreads();
#pragma unroll
            for (int i = 0; i < 8; i++) {
                int idx = tid + i * 256;
                sm.p1.W2[idx >> 6][idx & 63] = pk(wr[i], wr[i]);
                sm.p1.X_s[idx >> 5][idx & 31] = xr[i];
            }
            __syncthreads();
            if (t < 7) {
                const int fb = (t + 1) * 64;
#pragma unroll
                for (int i = 0; i < 8; i++) {
                    int idx = tid + i * 256;
                    wr[i] = W[(idx >> 6) * FEAT + fb + (idx & 63)];
                    xr[i] = x[((size_t)b * FEAT + fb + (idx >> 5)) * NUM + n0 + (idx & 31)];
                }
            }
#pragma unroll 8
            for (int fl = 0; fl < 64; fl++) {
                ull wvv = sm.p1.W2[lane][fl];                                             // LDS64, conflict-free
                ulonglong2 xp = *reinterpret_cast<const ulonglong2*>(&sm.p1.X_s[fl][w * 4]); // LDS128 broadcast
                ffma2(acc01, wvv, xp.x);
                ffma2(acc23, wvv, xp.y);
            }
        }

        float l[4];
        upk(l[0], l[1], acc01);
        upk(l[2], l[3], acc23);

        const float bv = bias[lane];
        float pa = 0.f;
#pragma unroll
        for (int j = 0; j < 4; j++) {
            float lg = l[j] + bv;
            float m = wmax(lg);
            float e = __expf(lg - m);
            float s = wsum(e);
            float a = e / s;
            int   n = n0 + w * 4 + j;
            g_a[((size_t)b * NUM + n) * KK + lane] = a;   // coalesced (k contiguous)
            pa += a;
        }
        sm.p1.red[w][lane] = pa;
        __syncthreads();
        if (tid < 32) {
            float s = 0.f;
#pragma unroll
            for (int g = 0; g < 8; g++) s += sm.p1.red[g][tid];
            g_asumt[((size_t)b * KK + tid) * 16 + tile] = s;   // transposed write
        }
    }

    // pre-barrier prefetch of phase-2 X tile c=0 (x is const input, no dependency)
    float xr2[8];
#pragma unroll
    for (int i = 0; i < 8; i++) {
        int idx = tid + i * 256;
        xr2[i] = x[((size_t)b2 * FEAT + f02 + (idx >> 5)) * NUM + nb2 + (idx & 31)];
    }

    gridbar();

    // ================= PHASE 2: ax / ax2 GEMM partials ========================
    {
        const int fw = w & 1, kg = w >> 1;
        const int fl = fw * 32 + lane;     // f within tile
        const int kbase = kg * 8;          // 8 k's = 4 packed pairs per thread

        float ar[4];
#pragma unroll
        for (int i = 0; i < 4; i++) {
            int idx = tid + i * 256;
            ar[i] = g_a[((size_t)b2 * NUM + nb2 + (idx >> 5)) * KK + (idx & 31)];
        }

        ull acc1[4] = {0ULL, 0ULL, 0ULL, 0ULL};
        ull acc2[4] = {0ULL, 0ULL, 0ULL, 0ULL};

        for (int c = 0; c < 4; c++) {
            __syncthreads();
#pragma unroll
            for (int i = 0; i < 4; i++) {
                int idx = tid + i * 256;
                sm.p2.A_s[idx >> 5][idx & 31] = ar[i];
            }
#pragma unroll
            for (int i = 0; i < 8; i++) {
                int idx = tid + i * 256;
                sm.p2.X2[idx >> 5][idx & 31] = pk(xr2[i], xr2[i]);
            }
            __syncthreads();
            if (c < 3) {
                const int n0 = nb2 + (c + 1) * 32;
#pragma unroll
                for (int i = 0; i < 4; i++) {
                    int idx = tid + i * 256;
                    ar[i] = g_a[((size_t)b2 * NUM + n0 + (idx >> 5)) * KK + (idx & 31)];
                }
#pragma unroll
                for (int i = 0; i < 8; i++) {
                    int idx = tid + i * 256;
                    xr2[i] = x[((size_t)b2 * FEAT + f02 + (idx >> 5)) * NUM + n0 + (idx & 31)];
                }
            }
#pragma unroll 4
            for (int nl = 0; nl < 32; nl++) {
                ull xvv  = sm.p2.X2[fl][nl];     // LDS64, conflict-free
                ull x2vv = fmul2(xvv, xvv);      // packed x^2
                ulonglong2 a01 = *reinterpret_cast<const ulonglong2*>(&sm.p2.A_s[nl][kbase]);     // broadcast
                ulonglong2 a23 = *reinterpret_cast<const ulonglong2*>(&sm.p2.A_s[nl][kbase + 4]); // broadcast
                ffma2(acc1[0], a01.x, xvv);  ffma2(acc2[0], a01.x, x2vv);
                ffma2(acc1[1], a01.y, xvv);  ffma2(acc2[1], a01.y, x2vv);
                ffma2(acc1[2], a23.x, xvv);  ffma2(acc2[2], a23.x, x2vv);
                ffma2(acc1[3], a23.y, xvv);  ffma2(acc2[3], a23.y, x2vv);
            }
        }

        const size_t base = (((size_t)s2 * BATCH + b2) * FEAT + f02 + fl) * KK + kbase;
        *reinterpret_cast<ulonglong2*>(&g_axp[base])      = make_ulonglong2(acc1[0], acc1[1]);
        *reinterpret_cast<ulonglong2*>(&g_axp[base + 4])  = make_ulonglong2(acc1[2], acc1[3]);
        *reinterpret_cast<ulonglong2*>(&g_ax2p[base])     = make_ulonglong2(acc2[0], acc2[1]);
        *reinterpret_cast<ulonglong2*>(&g_ax2p[base + 4]) = make_ulonglong2(acc2[2], acc2[3]);
    }

    gridbar();

    // ================= PHASE 3: fisher vectors + rownorm + const scale ========
    // 256 CTAs, 2 fg units each (8 f's per unit): b = bx>>5, fgbase = (bx&31)*2.
    {
        const int b      = bx >> 5;
        const int fgbase = (bx & 31) * 2;

        // asum[b][k]: 16 contiguous partials -> 4x LDG.128
        float asv = 0.f;
        {
            const float4* p = reinterpret_cast<const float4*>(&g_asumt[((size_t)b * KK + lane) * 16]);
#pragma unroll
            for (int q = 0; q < 4; q++) {
                float4 v = p[q];
                asv += (v.x + v.y) + (v.z + v.w);
            }
        }

#pragma unroll
        for (int j = 0; j < 2; j++) {
            const int f = (fgbase + j) * 8 + w;
            float ax = 0.f, ax2 = 0.f;
#pragma unroll
            for (int s = 0; s < NSPLIT; s++) {
                size_t po = (((size_t)s * BATCH + b) * FEAT + f) * KK + lane;
                ax  += g_axp[po];
                ax2 += g_ax2p[po];
            }
            float muv = mu[f * KK + lane];
            float sg  = sigma[f * KK + lane];
            float fv1 = (ax - muv * asv) / sg;
            float fv2 = (ax2 - 2.f * muv * ax + muv * muv * asv) / (sg * sg) - asv;

            float n1 = sqrtf(wsum(fv1 * fv1));
            float n2 = sqrtf(wsum(fv2 * fv2));
            float v1 = fv1 / fmaxf(n1, 1e-12f) * GSC;
            float v2 = fv2 / fmaxf(n2, 1e-12f) * GSC;

            const size_t ob = (size_t)b * 2 * FEAT * KK;
            out[ob + (size_t)f * KK + lane]             = v1;
            out[ob + FEAT * KK + (size_t)f * KK + lane] = v2;
        }
    }
}

// ---------------- launch -----------------------------------------------------
extern "C" void kernel_launch(void* const* d_in, const int* in_sizes, int n_in,
                              void* d_out, int out_size) {
    (void)in_sizes; (void)n_in; (void)out_size;
    const float* x     = (const float*)d_in[0];
    const float* W     = (const float*)d_in[1];
    const float* bias  = (const float*)d_in[2];
    const float* mu    = (const float*)d_in[3];
    const float* sigma = (const float*)d_in[4];
    float* out = (float*)d_out;

    k_all<<<NBLK, 256>>>(x, W, bias, mu, sigma, out);
}